// round 7
// baseline (speedup 1.0000x reference)
#include <cuda_runtime.h>
#include <math.h>
#include <stdint.h>

typedef unsigned long long u64;

// Problem constants
constexpr int kB   = 4;
constexpr int kN   = 1024;
constexpr int kHID = 256;
constexpr int kNH  = 8;
constexpr int kROWS = kB * kN;          // 4096
constexpr int kT    = 2048;             // bias table resolution
constexpr int kQT   = 64;               // queries per CTA
constexpr int kKT   = 128;              // keys per tile

// ---- packed f32x2 helpers ----
#define PACK2(out, lo, hi) \
    asm("mov.b64 %0, {%1, %2};" : "=l"(out) : "f"(lo), "f"(hi))
#define UNPACK2(lo, hi, v) \
    asm("mov.b64 {%0, %1}, %2;" : "=f"(lo), "=f"(hi) : "l"(v))
#define FMA2(acc, a, b) \
    asm("fma.rn.f32x2 %0, %1, %2, %0;" : "+l"(acc) : "l"(a), "l"(b))
#define MUL2(out, a, b) \
    asm("mul.rn.f32x2 %0, %1, %2;" : "=l"(out) : "l"(a), "l"(b))

// ---- smem layout (floats) for attn ----
constexpr int OFF_QS  = 0;                    // Qs[32][68]
constexpr int OFF_KT  = 2176;                 // Kt[32][132]  d-major, k-pairs
constexpr int OFF_VS  = 6400;                 // Vs[128][36]
constexpr int OFF_PU  = 11008;                // P[64][132] | red 4*2113
constexpr int OFF_TB  = 19460;                // tabd float2[2048] interleaved
constexpr int OFF_CK  = 23556;                // key coords [128]
constexpr int OFF_MK  = 23684;                // key mask   [128]
constexpr int OFF_M   = 23812;                // m[64]
constexpr int OFF_L   = 23876;                // l[64]
constexpr int OFF_CR  = 23940;                // corr[64]
constexpr int OFF_CQ  = 24004;                // cq[64]
constexpr int ATTN_SMEM = 24068 * 4;          // 96272 bytes

// ---------------- scratch (no allocations allowed) ----------------
__device__ float g_xln[kROWS * kHID];        // layernormed x
__device__ float g_qkv[kROWS * 3 * kHID];    // qkv projection
__device__ float g_tab[kNH * kT];            // bias table, HEAD-MAJOR, pre-scaled log2e
__device__ float g_ao [kROWS * kHID];        // attention output (pre-proj)

// ---------------- LayerNorm ----------------
__global__ void ln_kernel(const float* __restrict__ hin,
                          const float* __restrict__ gamma,
                          const float* __restrict__ beta)
{
    __shared__ float red[16];
    int row = blockIdx.x, t = threadIdx.x;
    float x = hin[(size_t)row * kHID + t];
    float s = x, s2 = x * x;
    #pragma unroll
    for (int off = 16; off; off >>= 1) {
        s  += __shfl_xor_sync(0xffffffffu, s,  off);
        s2 += __shfl_xor_sync(0xffffffffu, s2, off);
    }
    if ((t & 31) == 0) { red[t >> 5] = s; red[8 + (t >> 5)] = s2; }
    __syncthreads();
    float sum = 0.f, sum2 = 0.f;
    #pragma unroll
    for (int i = 0; i < 8; i++) { sum += red[i]; sum2 += red[8 + i]; }
    float mu  = sum * (1.0f / 256.0f);
    float var = sum2 * (1.0f / 256.0f) - mu * mu;
    float r   = rsqrtf(var + 1e-5f);
    g_xln[(size_t)row * kHID + t] = (x - mu) * r * gamma[t] + beta[t];
}

// ---------------- bias-table build: f(d) for d in [-1,1], kT pts, head-major ----------------
__global__ void __launch_bounds__(256) tab_kernel(
    const float* __restrict__ Wb1, const float* __restrict__ bb1,
    const float* __restrict__ Wb2, const float* __restrict__ bb2,
    const float* __restrict__ Wb3, const float* __restrict__ bb3)
{
    __shared__ float w1[64], c1[64], w2[64 * 64], c2[64], w3[64 * 8], c3[8];
    int t = threadIdx.x;
    if (t < 64) { w1[t] = Wb1[t]; c1[t] = bb1[t]; c2[t] = bb2[t]; }
    if (t < 8)  c3[t] = bb3[t];
    for (int i = t; i < 4096; i += 256) w2[i] = Wb2[i];
    for (int i = t; i < 512;  i += 256) w3[i] = Wb3[i];
    __syncthreads();

    int idx = blockIdx.x * 256 + t;
    float d = -1.0f + 2.0f * (float)idx / (float)(kT - 1);

    float h1[64];
    #pragma unroll
    for (int u = 0; u < 64; u++) {
        float a = fmaf(d, w1[u], c1[u]);
        h1[u] = a / (1.0f + expf(-a));           // silu
    }
    float acc[8];
    #pragma unroll
    for (int m = 0; m < 8; m++) acc[m] = c3[m];
    for (int u2 = 0; u2 < 64; u2++) {
        float a = c2[u2];
        #pragma unroll
        for (int u = 0; u < 64; u++) a = fmaf(h1[u], w2[u * 64 + u2], a);
        float sv = a / (1.0f + expf(-a));        // silu
        #pragma unroll
        for (int m = 0; m < 8; m++) acc[m] = fmaf(sv, w3[u2 * 8 + m], acc[m]);
    }
    const float LOG2E = 1.4426950408889634f;
    #pragma unroll
    for (int m = 0; m < 8; m++) g_tab[m * kT + idx] = acc[m] * LOG2E;
}

// ---------------- fp32 GEMM with packed FFMA2: C = A@W + bias (+resid) ----------------
__global__ void __launch_bounds__(256) gemm64(
    const float* __restrict__ A, const float* __restrict__ W,
    const float* __restrict__ bias, const float* __restrict__ resid,
    float* __restrict__ C, int M, int Nc, int K)
{
    __shared__ float As[16][64];
    __shared__ float Bs[16][64];
    int t  = threadIdx.x;
    int n0 = blockIdx.x * 64, m0 = blockIdx.y * 64;
    int tm = t >> 4, tn = t & 15;
    int am = t >> 2, ak4 = (t & 3) * 4;
    int bk = t >> 4, bn4 = (t & 15) * 4;

    u64 acc2[4][2] = {};
    for (int k0 = 0; k0 < K; k0 += 16) {
        float4 av = *(const float4*)(A + (size_t)(m0 + am) * K + k0 + ak4);
        float4 bv = *(const float4*)(W + (size_t)(k0 + bk) * Nc + n0 + bn4);
        As[ak4 + 0][am] = av.x; As[ak4 + 1][am] = av.y;
        As[ak4 + 2][am] = av.z; As[ak4 + 3][am] = av.w;
        *(float4*)&Bs[bk][bn4] = bv;
        __syncthreads();
        #pragma unroll
        for (int k = 0; k < 16; k++) {
            float4 a4 = *(const float4*)&As[k][tm * 4];
            const u64* bp = (const u64*)&Bs[k][tn * 4];
            u64 b01 = bp[0], b23 = bp[1];
            float ar[4] = {a4.x, a4.y, a4.z, a4.w};
            #pragma unroll
            for (int i = 0; i < 4; i++) {
                u64 ap; PACK2(ap, ar[i], ar[i]);
                FMA2(acc2[i][0], ap, b01);
                FMA2(acc2[i][1], ap, b23);
            }
        }
        __syncthreads();
    }
    #pragma unroll
    for (int i = 0; i < 4; i++) {
        int gm = m0 + tm * 4 + i;
        float cv[4];
        UNPACK2(cv[0], cv[1], acc2[i][0]);
        UNPACK2(cv[2], cv[3], acc2[i][1]);
        #pragma unroll
        for (int j = 0; j < 4; j++) {
            int gn = n0 + tn * 4 + j;
            float v = cv[j] + bias[gn];
            if (resid) v += resid[(size_t)gm * Nc + gn];
            C[(size_t)gm * Nc + gn] = v;
        }
    }
}

// ---------------- fused flash attention, FFMA2-packed register tiles ----------------
// CTA = (qtile=64, head, batch); 256 threads; 8 key-tiles of 128.
__global__ void __launch_bounds__(256, 2) attn_kernel(
    const float* __restrict__ coord, const int* __restrict__ mask)
{
    extern __shared__ float sm[];
    float* Qs  = sm + OFF_QS;     // [32][68] d-major
    float* Kt  = sm + OFF_KT;     // [32][132] d-major (keys along row, pairs)
    float* Vs  = sm + OFF_VS;     // [128][36] k-major
    float* PU  = sm + OFF_PU;     // P[64][132] | red (kc*2113 + q*33 + d)
    float* TB  = sm + OFF_TB;     // interleaved table pairs (f[i], f[i+1])
    float* ck  = sm + OFF_CK;
    int*   mkk = (int*)(sm + OFF_MK);
    float* msm = sm + OFF_M;
    float* lsm = sm + OFF_L;
    float* csm = sm + OFF_CR;
    float* cqs = sm + OFF_CQ;

    const int qt = blockIdx.x, h = blockIdx.y, b = blockIdx.z;
    const int q0 = qt * kQT;
    const int t  = threadIdx.x;

    const int tq = t >> 4;           // 0..15 : 4-query group
    const int tk = t & 15;           // 0..15 : key-pair group (QK)
    const int kc = t & 3;            // 0..3  : AV k-class
    const int td = (t >> 2) & 3;     // 0..3  : AV d-pair group

    const float QSCALE = 1.4426950408889634f / 5.656854249492381f; // log2e/sqrt(32)

    // ---- one-time: stage Q (d-major, pre-scaled), table pairs, init m/l ----
    for (int idx = t; idx < kQT * 32; idx += 256) {
        int q = idx >> 5, d = idx & 31;
        Qs[d * 68 + q] = g_qkv[((size_t)(b * kN + q0 + q)) * 768 + h * 32 + d] * QSCALE;
    }
    #pragma unroll
    for (int it = 0; it < 8; it++) {
        int i = t + it * 256;
        float f0 = g_tab[h * kT + i];
        float f1 = g_tab[h * kT + (i < kT - 1 ? i + 1 : kT - 1)];
        u64 pr; PACK2(pr, f0, f1);
        *(u64*)&TB[2 * i] = pr;
    }
    if (t < 64) {
        msm[t] = -1e30f;
        lsm[t] = 0.f;
        cqs[t] = coord[b * kN + q0 + t];
    }

    u64 o2[4][4] = {};   // 4 q-rows x 4 packed d-pairs (d = 2*td+8u, +1)

    for (int j0 = 0; j0 < kN; j0 += kKT) {
        // ---- stage K (transposed to d-major k-pairs) ----
        #pragma unroll
        for (int it = 0; it < 2; it++) {
            int w = t + it * 256;           // 0..511
            int p = w >> 3;                 // key pair 0..63
            int d4 = (w & 7) * 4;
            const float* r0 = g_qkv + ((size_t)(b * kN + j0 + 2 * p)) * 768 + h * 32 + d4;
            float4 k0 = *(const float4*)(r0 + 256);
            float4 k1 = *(const float4*)(r0 + 256 + 768);
            float a0[4] = {k0.x, k0.y, k0.z, k0.w};
            float a1[4] = {k1.x, k1.y, k1.z, k1.w};
            #pragma unroll
            for (int dd = 0; dd < 4; dd++) {
                u64 pr; PACK2(pr, a0[dd], a1[dd]);
                *(u64*)&Kt[(d4 + dd) * 132 + 2 * p] = pr;
            }
        }
        // ---- stage V (k-major) ----
        #pragma unroll
        for (int it = 0; it < 4; it++) {
            int idx = t + it * 256;
            int j = idx >> 3, d4 = (idx & 7) * 4;
            const float* rowp = g_qkv + ((size_t)(b * kN + j0 + j)) * 768 + h * 32 + d4;
            *(float4*)&Vs[j * 36 + d4] = *(const float4*)(rowp + 512);
        }
        if (t < 128) {
            ck[t]  = coord[b * kN + j0 + t];
            mkk[t] = mask [b * kN + j0 + t];
        }
        __syncthreads();

        // ---- QK^T: acc2[4 q][4 key-pairs], keys 2(tk+16jp), +1 ----
        u64 acc2[4][4] = {};
        #pragma unroll 4
        for (int d = 0; d < 32; d++) {
            float4 q4 = *(const float4*)&Qs[d * 68 + tq * 4];
            const float* krow = &Kt[d * 132 + 2 * tk];
            u64 kp0 = *(const u64*)(krow);
            u64 kp1 = *(const u64*)(krow + 32);
            u64 kp2 = *(const u64*)(krow + 64);
            u64 kp3 = *(const u64*)(krow + 96);
            float qa[4] = {q4.x, q4.y, q4.z, q4.w};
            #pragma unroll
            for (int i = 0; i < 4; i++) {
                u64 qq; PACK2(qq, qa[i], qa[i]);
                FMA2(acc2[i][0], qq, kp0);
                FMA2(acc2[i][1], qq, kp1);
                FMA2(acc2[i][2], qq, kp2);
                FMA2(acc2[i][3], qq, kp3);
            }
        }
        // store raw S (packed pairs) to P
        #pragma unroll
        for (int i = 0; i < 4; i++) {
            float* prow = &PU[(tq * 4 + i) * 132 + 2 * tk];
            *(u64*)(prow)      = acc2[i][0];
            *(u64*)(prow + 32) = acc2[i][1];
            *(u64*)(prow + 64) = acc2[i][2];
            *(u64*)(prow + 96) = acc2[i][3];
        }
        __syncthreads();

        // ---- per-row: bias add + mask + online-softmax (row r = t>>2) ----
        {
            int r  = t >> 2;
            int l4 = t & 3;
            float cq    = cqs[r];
            float m_old = msm[r];
            float tmax  = -1e30f;
            float* prow = PU + r * 132;
            #pragma unroll 4
            for (int cidx = 0; cidx < 32; cidx++) {
                int c = l4 * 8 + (((cidx & 7) + r) & 7) + ((cidx >> 3) << 5);
                float s;
                if (mkk[c] == 0) {
                    s = -1e38f;
                } else {
                    float dd = ck[c] - cq;
                    float u  = fmaf(dd, 1023.5f, 1023.5f);
                    int i0 = (int)u;
                    i0 = i0 < 0 ? 0 : (i0 > kT - 2 ? kT - 2 : i0);
                    float fr = u - (float)i0;
                    float b0, b1;
                    u64 bb = *(const u64*)&TB[2 * i0];
                    UNPACK2(b0, b1, bb);
                    s = prow[c] + fmaf(fr, b1 - b0, b0);
                }
                prow[c] = s;
                tmax = fmaxf(tmax, s);
            }
            tmax = fmaxf(tmax, __shfl_xor_sync(0xffffffffu, tmax, 1));
            tmax = fmaxf(tmax, __shfl_xor_sync(0xffffffffu, tmax, 2));
            float m_new = fmaxf(m_old, tmax);
            float corr  = exp2f(m_old - m_new);
            float sum = 0.f;
            #pragma unroll 4
            for (int cidx = 0; cidx < 32; cidx++) {
                int c = l4 * 8 + (((cidx & 7) + r) & 7) + ((cidx >> 3) << 5);
                float p = exp2f(prow[c] - m_new);
                prow[c] = p;
                sum += p;
            }
            sum += __shfl_xor_sync(0xffffffffu, sum, 1);
            sum += __shfl_xor_sync(0xffffffffu, sum, 2);
            if (l4 == 0) {
                msm[r] = m_new;
                lsm[r] = lsm[r] * corr + sum;
                csm[r] = corr;
            }
        }
        __syncthreads();

        // ---- rescale O (packed), then AV with conflict-free k ordering ----
        #pragma unroll
        for (int i = 0; i < 4; i++) {
            float corr = csm[tq * 4 + i];
            u64 cp; PACK2(cp, corr, corr);
            #pragma unroll
            for (int u = 0; u < 4; u++) MUL2(o2[i][u], o2[i][u], cp);
        }
        #pragma unroll 4
        for (int kk = 0; kk < 32; kk++) {
            int s = (kk + 2 * td + tq) & 31;
            int k = kc + 4 * s;
            float p[4];
            #pragma unroll
            for (int i = 0; i < 4; i++) p[i] = PU[(tq * 4 + i) * 132 + k];
            const float* vrow = &Vs[k * 36 + 2 * td];
            u64 v0 = *(const u64*)(vrow);
            u64 v1 = *(const u64*)(vrow + 8);
            u64 v2 = *(const u64*)(vrow + 16);
            u64 v3 = *(const u64*)(vrow + 24);
            #pragma unroll
            for (int i = 0; i < 4; i++) {
                u64 pp; PACK2(pp, p[i], p[i]);
                FMA2(o2[i][0], pp, v0);
                FMA2(o2[i][1], pp, v1);
                FMA2(o2[i][2], pp, v2);
                FMA2(o2[i][3], pp, v3);
            }
        }
        __syncthreads();   // P/K/V free for next tile
    }

    // ---- reduce 4 k-class partials via smem, normalize, write out ----
    float* red = PU;   // kc stride 2113, q stride 33
    #pragma unroll
    for (int i = 0; i < 4; i++) {
        #pragma unroll
        for (int u = 0; u < 4; u++) {
            float lo, hi;
            UNPACK2(lo, hi, o2[i][u]);
            int d = 8 * u + 2 * td;
            red[kc * 2113 + (tq * 4 + i) * 33 + d]     = lo;
            red[kc * 2113 + (tq * 4 + i) * 33 + d + 1] = hi;
        }
    }
    __syncthreads();
    {
        int q  = t >> 2;
        int d0 = (t & 3) * 8;
        float inv = 1.0f / lsm[q];
        float res[8];
        #pragma unroll
        for (int j = 0; j < 8; j++) {
            float s = 0.f;
            #pragma unroll
            for (int c = 0; c < 4; c++) s += red[c * 2113 + q * 33 + d0 + j];
            res[j] = s * inv;
        }
        float* orow = g_ao + ((size_t)(b * kN + q0 + q)) * 256 + h * 32 + d0;
        float4 w0 = {res[0], res[1], res[2], res[3]};
        float4 w1 = {res[4], res[5], res[6], res[7]};
        *(float4*)(orow)     = w0;
        *(float4*)(orow + 4) = w1;
    }
}

// ---------------- launch ----------------
extern "C" void kernel_launch(void* const* d_in, const int* in_sizes, int n_in,
                              void* d_out, int out_size)
{
    const float* hin   = (const float*)d_in[0];
    const float* coord = (const float*)d_in[1];
    const int*   mask  = (const int*)  d_in[2];
    const float* Wqkv  = (const float*)d_in[3];
    const float* bqkv  = (const float*)d_in[4];
    const float* Wproj = (const float*)d_in[5];
    const float* bproj = (const float*)d_in[6];
    const float* gamma = (const float*)d_in[7];
    const float* beta  = (const float*)d_in[8];
    const float* Wb1   = (const float*)d_in[9];
    const float* bb1   = (const float*)d_in[10];
    const float* Wb2   = (const float*)d_in[11];
    const float* bb2   = (const float*)d_in[12];
    const float* Wb3   = (const float*)d_in[13];
    const float* bb3   = (const float*)d_in[14];
    float* out = (float*)d_out;

    void *p_xln, *p_qkv, *p_ao;
    cudaGetSymbolAddress(&p_xln, g_xln);
    cudaGetSymbolAddress(&p_qkv, g_qkv);
    cudaGetSymbolAddress(&p_ao,  g_ao);

    cudaFuncSetAttribute(attn_kernel, cudaFuncAttributeMaxDynamicSharedMemorySize, ATTN_SMEM);

    // independent: bias table
    tab_kernel<<<kT / 256, 256>>>(Wb1, bb1, Wb2, bb2, Wb3, bb3);
    // layernorm
    ln_kernel<<<kROWS, 256>>>(hin, gamma, beta);
    // qkv = xln @ Wqkv + bqkv
    gemm64<<<dim3(768 / 64, kROWS / 64), 256>>>((const float*)p_xln, Wqkv, bqkv, nullptr,
                                                (float*)p_qkv, kROWS, 768, 256);
    // fused bias-lookup flash attention (FFMA2 register-tiled)
    attn_kernel<<<dim3(kN / kQT, kNH, kB), 256, ATTN_SMEM>>>(coord, mask);
    // out = h + ao @ Wproj + bproj
    gemm64<<<dim3(256 / 64, kROWS / 64), 256>>>((const float*)p_ao, Wproj, bproj, hin,
                                                out, kROWS, 256, 256);
}

// round 8
// speedup vs baseline: 1.0002x; 1.0002x over previous
#include <cuda_runtime.h>
#include <math.h>
#include <stdint.h>

typedef unsigned long long u64;

// Problem constants
constexpr int kB   = 4;
constexpr int kN   = 1024;
constexpr int kHID = 256;
constexpr int kNH  = 8;
constexpr int kROWS = kB * kN;          // 4096
constexpr int kT    = 2048;             // bias table resolution
constexpr int kQT   = 64;               // queries per CTA
constexpr int kKT   = 128;              // keys per tile

// ---- packed f32x2 helpers ----
#define PACK2(out, lo, hi) \
    asm("mov.b64 %0, {%1, %2};" : "=l"(out) : "f"(lo), "f"(hi))
#define UNPACK2(lo, hi, v) \
    asm("mov.b64 {%0, %1}, %2;" : "=f"(lo), "=f"(hi) : "l"(v))
#define FMA2(acc, a, b) \
    asm("fma.rn.f32x2 %0, %1, %2, %0;" : "+l"(acc) : "l"(a), "l"(b))
#define MUL2(out, a, b) \
    asm("mul.rn.f32x2 %0, %1, %2;" : "=l"(out) : "l"(a), "l"(b))

// ---- smem layout (floats) for attn ----
constexpr int OFF_QS  = 0;                    // Qs[32][68]
constexpr int OFF_KT  = 2176;                 // Kt[32][132]  d-major, k-pairs
constexpr int OFF_VS  = 6400;                 // Vs[128][36]
constexpr int OFF_PU  = 11008;                // P[64][132] | red 4*2113
constexpr int OFF_TB  = 19460;                // tabd float2[2048] interleaved
constexpr int OFF_CK  = 23556;                // key coords [128]
constexpr int OFF_MK  = 23684;                // key mask   [128]
constexpr int OFF_M   = 23812;                // m[64]
constexpr int OFF_L   = 23876;                // l[64]
constexpr int OFF_CR  = 23940;                // corr[64]
constexpr int OFF_CQ  = 24004;                // cq[64]
constexpr int ATTN_SMEM = 24068 * 4;          // 96272 bytes

// ---------------- scratch (no allocations allowed) ----------------
__device__ float g_xln[kROWS * kHID];        // layernormed x
__device__ float g_qkv[kROWS * 3 * kHID];    // qkv projection
__device__ float g_tab[kNH * kT];            // bias table, HEAD-MAJOR, pre-scaled log2e
__device__ float g_ao [kROWS * kHID];        // attention output (pre-proj)

// ---------------- LayerNorm ----------------
__global__ void ln_kernel(const float* __restrict__ hin,
                          const float* __restrict__ gamma,
                          const float* __restrict__ beta)
{
    __shared__ float red[16];
    int row = blockIdx.x, t = threadIdx.x;
    float x = hin[(size_t)row * kHID + t];
    float s = x, s2 = x * x;
    #pragma unroll
    for (int off = 16; off; off >>= 1) {
        s  += __shfl_xor_sync(0xffffffffu, s,  off);
        s2 += __shfl_xor_sync(0xffffffffu, s2, off);
    }
    if ((t & 31) == 0) { red[t >> 5] = s; red[8 + (t >> 5)] = s2; }
    __syncthreads();
    float sum = 0.f, sum2 = 0.f;
    #pragma unroll
    for (int i = 0; i < 8; i++) { sum += red[i]; sum2 += red[8 + i]; }
    float mu  = sum * (1.0f / 256.0f);
    float var = sum2 * (1.0f / 256.0f) - mu * mu;
    float r   = rsqrtf(var + 1e-5f);
    g_xln[(size_t)row * kHID + t] = (x - mu) * r * gamma[t] + beta[t];
}

// ---------------- bias-table build: f(d) for d in [-1,1], kT pts, head-major ----------------
__global__ void __launch_bounds__(256) tab_kernel(
    const float* __restrict__ Wb1, const float* __restrict__ bb1,
    const float* __restrict__ Wb2, const float* __restrict__ bb2,
    const float* __restrict__ Wb3, const float* __restrict__ bb3)
{
    __shared__ float w1[64], c1[64], w2[64 * 64], c2[64], w3[64 * 8], c3[8];
    int t = threadIdx.x;
    if (t < 64) { w1[t] = Wb1[t]; c1[t] = bb1[t]; c2[t] = bb2[t]; }
    if (t < 8)  c3[t] = bb3[t];
    for (int i = t; i < 4096; i += 256) w2[i] = Wb2[i];
    for (int i = t; i < 512;  i += 256) w3[i] = Wb3[i];
    __syncthreads();

    int idx = blockIdx.x * 256 + t;
    float d = -1.0f + 2.0f * (float)idx / (float)(kT - 1);

    float h1[64];
    #pragma unroll
    for (int u = 0; u < 64; u++) {
        float a = fmaf(d, w1[u], c1[u]);
        h1[u] = a / (1.0f + expf(-a));           // silu
    }
    float acc[8];
    #pragma unroll
    for (int m = 0; m < 8; m++) acc[m] = c3[m];
    for (int u2 = 0; u2 < 64; u2++) {
        float a = c2[u2];
        #pragma unroll
        for (int u = 0; u < 64; u++) a = fmaf(h1[u], w2[u * 64 + u2], a);
        float sv = a / (1.0f + expf(-a));        // silu
        #pragma unroll
        for (int m = 0; m < 8; m++) acc[m] = fmaf(sv, w3[u2 * 8 + m], acc[m]);
    }
    const float LOG2E = 1.4426950408889634f;
    #pragma unroll
    for (int m = 0; m < 8; m++) g_tab[m * kT + idx] = acc[m] * LOG2E;
}

// ---------------- fp32 GEMM with packed FFMA2: C = A@W + bias (+resid) ----------------
__global__ void __launch_bounds__(256) gemm64(
    const float* __restrict__ A, const float* __restrict__ W,
    const float* __restrict__ bias, const float* __restrict__ resid,
    float* __restrict__ C, int M, int Nc, int K)
{
    __shared__ float As[16][64];
    __shared__ float Bs[16][64];
    int t  = threadIdx.x;
    int n0 = blockIdx.x * 64, m0 = blockIdx.y * 64;
    int tm = t >> 4, tn = t & 15;
    int am = t >> 2, ak4 = (t & 3) * 4;
    int bk = t >> 4, bn4 = (t & 15) * 4;

    u64 acc2[4][2] = {};
    for (int k0 = 0; k0 < K; k0 += 16) {
        float4 av = *(const float4*)(A + (size_t)(m0 + am) * K + k0 + ak4);
        float4 bv = *(const float4*)(W + (size_t)(k0 + bk) * Nc + n0 + bn4);
        As[ak4 + 0][am] = av.x; As[ak4 + 1][am] = av.y;
        As[ak4 + 2][am] = av.z; As[ak4 + 3][am] = av.w;
        *(float4*)&Bs[bk][bn4] = bv;
        __syncthreads();
        #pragma unroll
        for (int k = 0; k < 16; k++) {
            float4 a4 = *(const float4*)&As[k][tm * 4];
            const u64* bp = (const u64*)&Bs[k][tn * 4];
            u64 b01 = bp[0], b23 = bp[1];
            float ar[4] = {a4.x, a4.y, a4.z, a4.w};
            #pragma unroll
            for (int i = 0; i < 4; i++) {
                u64 ap; PACK2(ap, ar[i], ar[i]);
                FMA2(acc2[i][0], ap, b01);
                FMA2(acc2[i][1], ap, b23);
            }
        }
        __syncthreads();
    }
    #pragma unroll
    for (int i = 0; i < 4; i++) {
        int gm = m0 + tm * 4 + i;
        float cv[4];
        UNPACK2(cv[0], cv[1], acc2[i][0]);
        UNPACK2(cv[2], cv[3], acc2[i][1]);
        #pragma unroll
        for (int j = 0; j < 4; j++) {
            int gn = n0 + tn * 4 + j;
            float v = cv[j] + bias[gn];
            if (resid) v += resid[(size_t)gm * Nc + gn];
            C[(size_t)gm * Nc + gn] = v;
        }
    }
}

// ---------------- fused flash attention, FFMA2-packed register tiles ----------------
// CTA = (qtile=64, head, batch); 256 threads; 8 key-tiles of 128.
__global__ void __launch_bounds__(256, 2) attn_kernel(
    const float* __restrict__ coord, const int* __restrict__ mask)
{
    extern __shared__ float sm[];
    float* Qs  = sm + OFF_QS;     // [32][68] d-major
    float* Kt  = sm + OFF_KT;     // [32][132] d-major (keys along row, pairs)
    float* Vs  = sm + OFF_VS;     // [128][36] k-major
    float* PU  = sm + OFF_PU;     // P[64][132] | red (kc*2113 + q*33 + d)
    float* TB  = sm + OFF_TB;     // interleaved table pairs (f[i], f[i+1])
    float* ck  = sm + OFF_CK;
    int*   mkk = (int*)(sm + OFF_MK);
    float* msm = sm + OFF_M;
    float* lsm = sm + OFF_L;
    float* csm = sm + OFF_CR;
    float* cqs = sm + OFF_CQ;

    const int qt = blockIdx.x, h = blockIdx.y, b = blockIdx.z;
    const int q0 = qt * kQT;
    const int t  = threadIdx.x;

    const int tq = t >> 4;           // 0..15 : 4-query group
    const int tk = t & 15;           // 0..15 : key-pair group (QK)
    const int kc = t & 3;            // 0..3  : AV k-class
    const int td = (t >> 2) & 3;     // 0..3  : AV d-pair group

    const float QSCALE = 1.4426950408889634f / 5.656854249492381f; // log2e/sqrt(32)

    // ---- one-time: stage Q (d-major, pre-scaled), table pairs, init m/l ----
    for (int idx = t; idx < kQT * 32; idx += 256) {
        int q = idx >> 5, d = idx & 31;
        Qs[d * 68 + q] = g_qkv[((size_t)(b * kN + q0 + q)) * 768 + h * 32 + d] * QSCALE;
    }
    #pragma unroll
    for (int it = 0; it < 8; it++) {
        int i = t + it * 256;
        float f0 = g_tab[h * kT + i];
        float f1 = g_tab[h * kT + (i < kT - 1 ? i + 1 : kT - 1)];
        u64 pr; PACK2(pr, f0, f1);
        *(u64*)&TB[2 * i] = pr;
    }
    if (t < 64) {
        msm[t] = -1e30f;
        lsm[t] = 0.f;
        cqs[t] = coord[b * kN + q0 + t];
    }

    u64 o2[4][4] = {};   // 4 q-rows x 4 packed d-pairs (d = 2*td+8u, +1)

    for (int j0 = 0; j0 < kN; j0 += kKT) {
        // ---- stage K (transposed to d-major k-pairs) ----
        #pragma unroll
        for (int it = 0; it < 2; it++) {
            int w = t + it * 256;           // 0..511
            int p = w >> 3;                 // key pair 0..63
            int d4 = (w & 7) * 4;
            const float* r0 = g_qkv + ((size_t)(b * kN + j0 + 2 * p)) * 768 + h * 32 + d4;
            float4 k0 = *(const float4*)(r0 + 256);
            float4 k1 = *(const float4*)(r0 + 256 + 768);
            float a0[4] = {k0.x, k0.y, k0.z, k0.w};
            float a1[4] = {k1.x, k1.y, k1.z, k1.w};
            #pragma unroll
            for (int dd = 0; dd < 4; dd++) {
                u64 pr; PACK2(pr, a0[dd], a1[dd]);
                *(u64*)&Kt[(d4 + dd) * 132 + 2 * p] = pr;
            }
        }
        // ---- stage V (k-major) ----
        #pragma unroll
        for (int it = 0; it < 4; it++) {
            int idx = t + it * 256;
            int j = idx >> 3, d4 = (idx & 7) * 4;
            const float* rowp = g_qkv + ((size_t)(b * kN + j0 + j)) * 768 + h * 32 + d4;
            *(float4*)&Vs[j * 36 + d4] = *(const float4*)(rowp + 512);
        }
        if (t < 128) {
            ck[t]  = coord[b * kN + j0 + t];
            mkk[t] = mask [b * kN + j0 + t];
        }
        __syncthreads();

        // ---- QK^T: acc2[4 q][4 key-pairs], keys 2(tk+16jp), +1 ----
        u64 acc2[4][4] = {};
        #pragma unroll 4
        for (int d = 0; d < 32; d++) {
            float4 q4 = *(const float4*)&Qs[d * 68 + tq * 4];
            const float* krow = &Kt[d * 132 + 2 * tk];
            u64 kp0 = *(const u64*)(krow);
            u64 kp1 = *(const u64*)(krow + 32);
            u64 kp2 = *(const u64*)(krow + 64);
            u64 kp3 = *(const u64*)(krow + 96);
            float qa[4] = {q4.x, q4.y, q4.z, q4.w};
            #pragma unroll
            for (int i = 0; i < 4; i++) {
                u64 qq; PACK2(qq, qa[i], qa[i]);
                FMA2(acc2[i][0], qq, kp0);
                FMA2(acc2[i][1], qq, kp1);
                FMA2(acc2[i][2], qq, kp2);
                FMA2(acc2[i][3], qq, kp3);
            }
        }
        // store raw S (packed pairs) to P
        #pragma unroll
        for (int i = 0; i < 4; i++) {
            float* prow = &PU[(tq * 4 + i) * 132 + 2 * tk];
            *(u64*)(prow)      = acc2[i][0];
            *(u64*)(prow + 32) = acc2[i][1];
            *(u64*)(prow + 64) = acc2[i][2];
            *(u64*)(prow + 96) = acc2[i][3];
        }
        __syncthreads();

        // ---- per-row: bias add + mask + online-softmax (row r = t>>2) ----
        {
            int r  = t >> 2;
            int l4 = t & 3;
            float cq    = cqs[r];
            float m_old = msm[r];
            float tmax  = -1e30f;
            float* prow = PU + r * 132;
            #pragma unroll 4
            for (int cidx = 0; cidx < 32; cidx++) {
                int c = l4 * 8 + (((cidx & 7) + r) & 7) + ((cidx >> 3) << 5);
                float s;
                if (mkk[c] == 0) {
                    s = -1e38f;
                } else {
                    float dd = ck[c] - cq;
                    float u  = fmaf(dd, 1023.5f, 1023.5f);
                    int i0 = (int)u;
                    i0 = i0 < 0 ? 0 : (i0 > kT - 2 ? kT - 2 : i0);
                    float fr = u - (float)i0;
                    float b0, b1;
                    u64 bb = *(const u64*)&TB[2 * i0];
                    UNPACK2(b0, b1, bb);
                    s = prow[c] + fmaf(fr, b1 - b0, b0);
                }
                prow[c] = s;
                tmax = fmaxf(tmax, s);
            }
            tmax = fmaxf(tmax, __shfl_xor_sync(0xffffffffu, tmax, 1));
            tmax = fmaxf(tmax, __shfl_xor_sync(0xffffffffu, tmax, 2));
            float m_new = fmaxf(m_old, tmax);
            float corr  = exp2f(m_old - m_new);
            float sum = 0.f;
            #pragma unroll 4
            for (int cidx = 0; cidx < 32; cidx++) {
                int c = l4 * 8 + (((cidx & 7) + r) & 7) + ((cidx >> 3) << 5);
                float p = exp2f(prow[c] - m_new);
                prow[c] = p;
                sum += p;
            }
            sum += __shfl_xor_sync(0xffffffffu, sum, 1);
            sum += __shfl_xor_sync(0xffffffffu, sum, 2);
            if (l4 == 0) {
                msm[r] = m_new;
                lsm[r] = lsm[r] * corr + sum;
                csm[r] = corr;
            }
        }
        __syncthreads();

        // ---- rescale O (packed), then AV with conflict-free k ordering ----
        #pragma unroll
        for (int i = 0; i < 4; i++) {
            float corr = csm[tq * 4 + i];
            u64 cp; PACK2(cp, corr, corr);
            #pragma unroll
            for (int u = 0; u < 4; u++) MUL2(o2[i][u], o2[i][u], cp);
        }
        #pragma unroll 4
        for (int kk = 0; kk < 32; kk++) {
            int s = (kk + 2 * td + tq) & 31;
            int k = kc + 4 * s;
            float p[4];
            #pragma unroll
            for (int i = 0; i < 4; i++) p[i] = PU[(tq * 4 + i) * 132 + k];
            const float* vrow = &Vs[k * 36 + 2 * td];
            u64 v0 = *(const u64*)(vrow);
            u64 v1 = *(const u64*)(vrow + 8);
            u64 v2 = *(const u64*)(vrow + 16);
            u64 v3 = *(const u64*)(vrow + 24);
            #pragma unroll
            for (int i = 0; i < 4; i++) {
                u64 pp; PACK2(pp, p[i], p[i]);
                FMA2(o2[i][0], pp, v0);
                FMA2(o2[i][1], pp, v1);
                FMA2(o2[i][2], pp, v2);
                FMA2(o2[i][3], pp, v3);
            }
        }
        __syncthreads();   // P/K/V free for next tile
    }

    // ---- reduce 4 k-class partials via smem, normalize, write out ----
    float* red = PU;   // kc stride 2113, q stride 33
    #pragma unroll
    for (int i = 0; i < 4; i++) {
        #pragma unroll
        for (int u = 0; u < 4; u++) {
            float lo, hi;
            UNPACK2(lo, hi, o2[i][u]);
            int d = 8 * u + 2 * td;
            red[kc * 2113 + (tq * 4 + i) * 33 + d]     = lo;
            red[kc * 2113 + (tq * 4 + i) * 33 + d + 1] = hi;
        }
    }
    __syncthreads();
    {
        int q  = t >> 2;
        int d0 = (t & 3) * 8;
        float inv = 1.0f / lsm[q];
        float res[8];
        #pragma unroll
        for (int j = 0; j < 8; j++) {
            float s = 0.f;
            #pragma unroll
            for (int c = 0; c < 4; c++) s += red[c * 2113 + q * 33 + d0 + j];
            res[j] = s * inv;
        }
        float* orow = g_ao + ((size_t)(b * kN + q0 + q)) * 256 + h * 32 + d0;
        float4 w0 = {res[0], res[1], res[2], res[3]};
        float4 w1 = {res[4], res[5], res[6], res[7]};
        *(float4*)(orow)     = w0;
        *(float4*)(orow + 4) = w1;
    }
}

// ---------------- launch ----------------
extern "C" void kernel_launch(void* const* d_in, const int* in_sizes, int n_in,
                              void* d_out, int out_size)
{
    const float* hin   = (const float*)d_in[0];
    const float* coord = (const float*)d_in[1];
    const int*   mask  = (const int*)  d_in[2];
    const float* Wqkv  = (const float*)d_in[3];
    const float* bqkv  = (const float*)d_in[4];
    const float* Wproj = (const float*)d_in[5];
    const float* bproj = (const float*)d_in[6];
    const float* gamma = (const float*)d_in[7];
    const float* beta  = (const float*)d_in[8];
    const float* Wb1   = (const float*)d_in[9];
    const float* bb1   = (const float*)d_in[10];
    const float* Wb2   = (const float*)d_in[11];
    const float* bb2   = (const float*)d_in[12];
    const float* Wb3   = (const float*)d_in[13];
    const float* bb3   = (const float*)d_in[14];
    float* out = (float*)d_out;

    void *p_xln, *p_qkv, *p_ao;
    cudaGetSymbolAddress(&p_xln, g_xln);
    cudaGetSymbolAddress(&p_qkv, g_qkv);
    cudaGetSymbolAddress(&p_ao,  g_ao);

    cudaFuncSetAttribute(attn_kernel, cudaFuncAttributeMaxDynamicSharedMemorySize, ATTN_SMEM);

    // independent: bias table
    tab_kernel<<<kT / 256, 256>>>(Wb1, bb1, Wb2, bb2, Wb3, bb3);
    // layernorm
    ln_kernel<<<kROWS, 256>>>(hin, gamma, beta);
    // qkv = xln @ Wqkv + bqkv
    gemm64<<<dim3(768 / 64, kROWS / 64), 256>>>((const float*)p_xln, Wqkv, bqkv, nullptr,
                                                (float*)p_qkv, kROWS, 768, 256);
    // fused bias-lookup flash attention (FFMA2 register-tiled)
    attn_kernel<<<dim3(kN / kQT, kNH, kB), 256, ATTN_SMEM>>>(coord, mask);
    // out = h + ao @ Wproj + bproj
    gemm64<<<dim3(256 / 64, kROWS / 64), 256>>>((const float*)p_ao, Wproj, bproj, hin,
                                                out, kROWS, 256, 256);
}

// round 11
// speedup vs baseline: 1.7144x; 1.7141x over previous
#include <cuda_runtime.h>
#include <cuda_bf16.h>
#include <math.h>
#include <stdint.h>

typedef unsigned long long u64;
typedef uint32_t u32;

constexpr int kB = 4, kN = 1024, kNH = 8, kHID = 256;
constexpr int kROWS = kB * kN;
constexpr int kT = 2048;

// smem byte offsets for attn (row stride 80B = 40 bf16, conflict-free for ldsm)
constexpr int SO_CK  = 16384, SO_MK = 16896;
constexpr int SO_QHI = 17408, SO_QLO = 27648;
constexpr int SO_KHI = 37888, SO_KLO = 48128;
constexpr int SO_VHI = 58368, SO_VLO = 68608;
constexpr int SMEM_BYTES = 78848;

__device__ float g_xln[kROWS * kHID];
__device__ float g_qkv[kROWS * 3 * kHID];
__device__ float g_tab[kNH * kT];            // head-major, log2e pre-scaled
__device__ float g_ao [kROWS * kHID];

// ---------------- helpers ----------------
__device__ __forceinline__ u32 smem_u32(const void* p) {
    u32 a;
    asm("{ .reg .u64 t; cvta.to.shared.u64 t, %1; cvt.u32.u64 %0, t; }" : "=r"(a) : "l"(p));
    return a;
}
__device__ __forceinline__ void ldsm_x4(u32* r, u32 a) {
    asm volatile("ldmatrix.sync.aligned.m8n8.x4.shared.b16 {%0,%1,%2,%3}, [%4];"
        : "=r"(r[0]), "=r"(r[1]), "=r"(r[2]), "=r"(r[3]) : "r"(a));
}
__device__ __forceinline__ void ldsm_x4_t(u32* r, u32 a) {
    asm volatile("ldmatrix.sync.aligned.m8n8.x4.trans.shared.b16 {%0,%1,%2,%3}, [%4];"
        : "=r"(r[0]), "=r"(r[1]), "=r"(r[2]), "=r"(r[3]) : "r"(a));
}
__device__ __forceinline__ void mma_bf16(float* d, const u32* a, u32 b0, u32 b1) {
    asm volatile(
        "mma.sync.aligned.m16n8k16.row.col.f32.bf16.bf16.f32 "
        "{%0,%1,%2,%3}, {%4,%5,%6,%7}, {%8,%9}, {%0,%1,%2,%3};"
        : "+f"(d[0]), "+f"(d[1]), "+f"(d[2]), "+f"(d[3])
        : "r"(a[0]), "r"(a[1]), "r"(a[2]), "r"(a[3]), "r"(b0), "r"(b1));
}
__device__ __forceinline__ float ex2(float x) {
    float y; asm("ex2.approx.f32 %0, %1;" : "=f"(y) : "f"(x)); return y;
}
__device__ __forceinline__ u32 pk2(float a, float b) {
    __nv_bfloat162 t = __floats2bfloat162_rn(a, b);
    return *reinterpret_cast<u32*>(&t);
}
__device__ __forceinline__ float lo_f(u32 h) { return __uint_as_float(h << 16); }
__device__ __forceinline__ float hi_f(u32 h) { return __uint_as_float(h & 0xffff0000u); }

// stage a [128 x 32] f32 tile (stride 768) into bf16 hi/lo smem, row stride 80B
__device__ __forceinline__ void stage_mat(const float* src, char* hib, char* lob,
                                          int t, float scale)
{
    #pragma unroll
    for (int i = 0; i < 4; i++) {
        int idx = t + i * 256;
        int row = idx >> 3, d4 = (idx & 7) * 4;
        float4 v = *(const float4*)(src + (size_t)row * 768 + d4);
        float x0 = v.x * scale, x1 = v.y * scale, x2 = v.z * scale, x3 = v.w * scale;
        u32 h01 = pk2(x0, x1), h23 = pk2(x2, x3);
        u32 l01 = pk2(x0 - lo_f(h01), x1 - hi_f(h01));
        u32 l23 = pk2(x2 - lo_f(h23), x3 - hi_f(h23));
        int off = row * 80 + d4 * 2;
        *(uint2*)(hib + off) = make_uint2(h01, h23);
        *(uint2*)(lob + off) = make_uint2(l01, l23);
    }
}

// ---------------- LayerNorm ----------------
__global__ void ln_kernel(const float* __restrict__ hin, const float* __restrict__ gamma,
                          const float* __restrict__ beta)
{
    __shared__ float red[16];
    int row = blockIdx.x, t = threadIdx.x;
    float x = hin[(size_t)row * kHID + t];
    float s = x, s2 = x * x;
    #pragma unroll
    for (int off = 16; off; off >>= 1) {
        s  += __shfl_xor_sync(0xffffffffu, s,  off);
        s2 += __shfl_xor_sync(0xffffffffu, s2, off);
    }
    if ((t & 31) == 0) { red[t >> 5] = s; red[8 + (t >> 5)] = s2; }
    __syncthreads();
    float sum = 0.f, sum2 = 0.f;
    #pragma unroll
    for (int i = 0; i < 8; i++) { sum += red[i]; sum2 += red[8 + i]; }
    float mu = sum * (1.f / 256.f);
    float var = sum2 * (1.f / 256.f) - mu * mu;
    float r = rsqrtf(var + 1e-5f);
    g_xln[(size_t)row * kHID + t] = (x - mu) * r * gamma[t] + beta[t];
}

// ---------------- bias table ----------------
__global__ void __launch_bounds__(256) tab_kernel(
    const float* __restrict__ Wb1, const float* __restrict__ bb1,
    const float* __restrict__ Wb2, const float* __restrict__ bb2,
    const float* __restrict__ Wb3, const float* __restrict__ bb3)
{
    __shared__ float w1[64], c1[64], w2[4096], c2[64], w3[512], c3[8];
    int t = threadIdx.x;
    if (t < 64) { w1[t] = Wb1[t]; c1[t] = bb1[t]; c2[t] = bb2[t]; }
    if (t < 8)  c3[t] = bb3[t];
    for (int i = t; i < 4096; i += 256) w2[i] = Wb2[i];
    for (int i = t; i < 512;  i += 256) w3[i] = Wb3[i];
    __syncthreads();
    int idx = blockIdx.x * 256 + t;
    float d = -1.f + 2.f * (float)idx / (float)(kT - 1);
    float h1[64];
    #pragma unroll
    for (int u = 0; u < 64; u++) {
        float a = fmaf(d, w1[u], c1[u]);
        h1[u] = a / (1.f + expf(-a));
    }
    float acc[8];
    #pragma unroll
    for (int m = 0; m < 8; m++) acc[m] = c3[m];
    for (int u2 = 0; u2 < 64; u2++) {
        float a = c2[u2];
        #pragma unroll
        for (int u = 0; u < 64; u++) a = fmaf(h1[u], w2[u * 64 + u2], a);
        float sv = a / (1.f + expf(-a));
        #pragma unroll
        for (int m = 0; m < 8; m++) acc[m] = fmaf(sv, w3[u2 * 8 + m], acc[m]);
    }
    #pragma unroll
    for (int m = 0; m < 8; m++) g_tab[m * kT + idx] = acc[m] * 1.4426950408889634f;
}

// ---------------- fp32 GEMM (FFMA2) ----------------
#define PACK2(o, a, b) asm("mov.b64 %0, {%1, %2};" : "=l"(o) : "f"(a), "f"(b))
#define UNPACK2(a, b, v) asm("mov.b64 {%0, %1}, %2;" : "=f"(a), "=f"(b) : "l"(v))
#define FMA2(acc, a, b) asm("fma.rn.f32x2 %0, %1, %2, %0;" : "+l"(acc) : "l"(a), "l"(b))

__global__ void __launch_bounds__(256) gemm64(
    const float* __restrict__ A, const float* __restrict__ W,
    const float* __restrict__ bias, const float* __restrict__ resid,
    float* __restrict__ C, int M, int Nc, int K)
{
    __shared__ float As[16][64], Bs[16][64];
    int t = threadIdx.x;
    int n0 = blockIdx.x * 64, m0 = blockIdx.y * 64;
    int tm = t >> 4, tn = t & 15;
    int am = t >> 2, ak4 = (t & 3) * 4;
    int bk = t >> 4, bn4 = (t & 15) * 4;
    u64 acc2[4][2] = {};
    for (int k0 = 0; k0 < K; k0 += 16) {
        float4 av = *(const float4*)(A + (size_t)(m0 + am) * K + k0 + ak4);
        float4 bv = *(const float4*)(W + (size_t)(k0 + bk) * Nc + n0 + bn4);
        As[ak4 + 0][am] = av.x; As[ak4 + 1][am] = av.y;
        As[ak4 + 2][am] = av.z; As[ak4 + 3][am] = av.w;
        *(float4*)&Bs[bk][bn4] = bv;
        __syncthreads();
        #pragma unroll
        for (int k = 0; k < 16; k++) {
            float4 a4 = *(const float4*)&As[k][tm * 4];
            const u64* bp = (const u64*)&Bs[k][tn * 4];
            u64 b01 = bp[0], b23 = bp[1];
            float ar[4] = {a4.x, a4.y, a4.z, a4.w};
            #pragma unroll
            for (int i = 0; i < 4; i++) {
                u64 ap; PACK2(ap, ar[i], ar[i]);
                FMA2(acc2[i][0], ap, b01);
                FMA2(acc2[i][1], ap, b23);
            }
        }
        __syncthreads();
    }
    #pragma unroll
    for (int i = 0; i < 4; i++) {
        int gm = m0 + tm * 4 + i;
        float cv[4];
        UNPACK2(cv[0], cv[1], acc2[i][0]);
        UNPACK2(cv[2], cv[3], acc2[i][1]);
        #pragma unroll
        for (int j = 0; j < 4; j++) {
            int gn = n0 + tn * 4 + j;
            float v = cv[j] + bias[gn];
            if (resid) v += resid[(size_t)gm * Nc + gn];
            C[(size_t)gm * Nc + gn] = v;
        }
    }
}

// ---------------- HMMA flash attention ----------------
// CTA = (128 q, head, batch), 8 warps; warp w owns rows 16w..16w+15.
__global__ void __launch_bounds__(256) attn_kernel(
    const float* __restrict__ coord, const int* __restrict__ mask)
{
    extern __shared__ char smc[];
    float2* TB2 = (float2*)smc;                 // [2048] pairs (f[i], f[i+1])
    float*  ck  = (float*)(smc + SO_CK);
    int*    mkp = (int*)(smc + SO_MK);
    const u32 smb = smem_u32(smc);

    const int qt = blockIdx.x, h = blockIdx.y, b = blockIdx.z;
    const int q0 = qt * 128;
    const int t = threadIdx.x, w = t >> 5, lane = t & 31;

    // stage bias-table pairs + Q hi/lo (scaled)
    #pragma unroll
    for (int i = 0; i < 8; i++) {
        int idx = t + i * 256;
        float f0 = g_tab[h * kT + idx];
        float f1 = g_tab[h * kT + (idx < kT - 1 ? idx + 1 : kT - 1)];
        TB2[idx] = make_float2(f0, f1);
    }
    const float QSCALE = 1.4426950408889634f / 5.656854249492381f;  // log2e/sqrt(32)
    stage_mat(g_qkv + (size_t)(b * kN + q0) * 768 + h * 32, smc + SO_QHI, smc + SO_QLO, t, QSCALE);
    __syncthreads();

    // Q A-fragments (persistent in registers)
    u32 aQh[2][4], aQl[2][4];
    {
        u32 qa = smb + SO_QHI + (16 * w + (lane & 15)) * 80 + ((lane >> 4) << 4);
        ldsm_x4(aQh[0], qa);
        ldsm_x4(aQh[1], qa + 32);
        ldsm_x4(aQl[0], qa + (SO_QLO - SO_QHI));
        ldsm_x4(aQl[1], qa + (SO_QLO - SO_QHI) + 32);
    }

    const int r1 = lane >> 2;                     // rows r1, r1+8 within warp tile
    const float cq1 = coord[b * kN + q0 + 16 * w + r1];
    const float cq2 = coord[b * kN + q0 + 16 * w + r1 + 8];
    const float aq1 = fmaf(-cq1, 1023.5f, 1023.5f);
    const float aq2 = fmaf(-cq2, 1023.5f, 1023.5f);

    float m1 = -1e30f, m2 = -1e30f, l1 = 0.f, l2 = 0.f;
    float o[4][4] = {};

    for (int tile = 0; tile < 8; tile++) {
        const int j0 = tile * 128;
        __syncthreads();                           // prior tile fully consumed
        stage_mat(g_qkv + (size_t)(b * kN + j0) * 768 + 256 + h * 32,
                  smc + SO_KHI, smc + SO_KLO, t, 1.f);
        stage_mat(g_qkv + (size_t)(b * kN + j0) * 768 + 512 + h * 32,
                  smc + SO_VHI, smc + SO_VLO, t, 1.f);
        if (t < 128) { ck[t] = coord[b * kN + j0 + t]; mkp[t] = mask[b * kN + j0 + t]; }
        __syncthreads();

        // ---- S = Q K^T (16 rows x 128 cols per warp) ----
        float sacc[16][4];
        #pragma unroll
        for (int i = 0; i < 16; i++)
            { sacc[i][0] = 0.f; sacc[i][1] = 0.f; sacc[i][2] = 0.f; sacc[i][3] = 0.f; }
        #pragma unroll
        for (int ks = 0; ks < 2; ks++) {
            #pragma unroll
            for (int nb = 0; nb < 8; nb++) {
                u32 kh[4], kl[4];
                u32 ka = smb + SO_KHI + (nb * 16 + (lane & 15)) * 80 + ks * 32 + ((lane >> 4) << 4);
                ldsm_x4(kh, ka);
                ldsm_x4(kl, ka + (SO_KLO - SO_KHI));
                mma_bf16(sacc[2 * nb],     aQh[ks], kh[0], kh[2]);
                mma_bf16(sacc[2 * nb + 1], aQh[ks], kh[1], kh[3]);
                mma_bf16(sacc[2 * nb],     aQl[ks], kh[0], kh[2]);
                mma_bf16(sacc[2 * nb + 1], aQl[ks], kh[1], kh[3]);
                mma_bf16(sacc[2 * nb],     aQh[ks], kl[0], kl[2]);
                mma_bf16(sacc[2 * nb + 1], aQh[ks], kl[1], kl[3]);
            }
        }

        // ---- softmax pass 1: bias add + mask + running max ----
        float mx1 = m1, mx2 = m2;
        #pragma unroll
        for (int cb = 0; cb < 16; cb++) {
            int c0 = cb * 8 + 2 * (lane & 3);
            float ck0 = ck[c0], ck1 = ck[c0 + 1];
            int mk0 = mkp[c0], mk1 = mkp[c0 + 1];
            float u00 = fmaf(ck0, 1023.5f, aq1), u01 = fmaf(ck1, 1023.5f, aq1);
            float u10 = fmaf(ck0, 1023.5f, aq2), u11 = fmaf(ck1, 1023.5f, aq2);
            int i00 = (int)u00, i01 = (int)u01, i10 = (int)u10, i11 = (int)u11;
            float2 t00 = TB2[i00], t01 = TB2[i01], t10 = TB2[i10], t11 = TB2[i11];
            float s00 = sacc[cb][0] + fmaf(u00 - (float)i00, t00.y - t00.x, t00.x);
            float s01 = sacc[cb][1] + fmaf(u01 - (float)i01, t01.y - t01.x, t01.x);
            float s10 = sacc[cb][2] + fmaf(u10 - (float)i10, t10.y - t10.x, t10.x);
            float s11 = sacc[cb][3] + fmaf(u11 - (float)i11, t11.y - t11.x, t11.x);
            if (!mk0) { s00 = -1e38f; s10 = -1e38f; }
            if (!mk1) { s01 = -1e38f; s11 = -1e38f; }
            sacc[cb][0] = s00; sacc[cb][1] = s01; sacc[cb][2] = s10; sacc[cb][3] = s11;
            mx1 = fmaxf(mx1, fmaxf(s00, s01));
            mx2 = fmaxf(mx2, fmaxf(s10, s11));
        }
        mx1 = fmaxf(mx1, __shfl_xor_sync(0xffffffffu, mx1, 1));
        mx1 = fmaxf(mx1, __shfl_xor_sync(0xffffffffu, mx1, 2));
        mx2 = fmaxf(mx2, __shfl_xor_sync(0xffffffffu, mx2, 1));
        mx2 = fmaxf(mx2, __shfl_xor_sync(0xffffffffu, mx2, 2));
        float co1 = ex2(m1 - mx1), co2 = ex2(m2 - mx2);
        m1 = mx1; m2 = mx2;
        #pragma unroll
        for (int db = 0; db < 4; db++) {
            o[db][0] *= co1; o[db][1] *= co1; o[db][2] *= co2; o[db][3] *= co2;
        }

        // ---- pass 2: p = exp2(s - m); build P hi/lo A-fragments in registers ----
        float su1 = 0.f, su2 = 0.f;
        u32 phi[32], plo[32];
        #pragma unroll
        for (int cb = 0; cb < 16; cb++) {
            float p00 = ex2(sacc[cb][0] - m1), p01 = ex2(sacc[cb][1] - m1);
            float p10 = ex2(sacc[cb][2] - m2), p11 = ex2(sacc[cb][3] - m2);
            su1 += p00 + p01; su2 += p10 + p11;
            u32 hA = pk2(p00, p01);
            phi[2 * cb] = hA;
            plo[2 * cb] = pk2(p00 - lo_f(hA), p01 - hi_f(hA));
            u32 hB = pk2(p10, p11);
            phi[2 * cb + 1] = hB;
            plo[2 * cb + 1] = pk2(p10 - lo_f(hB), p11 - hi_f(hB));
        }
        // NOTE: su1/su2 are quad-partial (each lane covers 32 of 128 cols).
        // Valid because co is quad-uniform; full-row l reduced once at the end.
        l1 = l1 * co1 + su1;
        l2 = l2 * co2 + su2;

        // ---- O += P V ----
        #pragma unroll
        for (int kc = 0; kc < 8; kc++) {
            #pragma unroll
            for (int dp = 0; dp < 2; dp++) {
                u32 vh[4], vl[4];
                u32 va = smb + SO_VHI + (16 * kc + (lane & 15)) * 80 + dp * 32 + ((lane >> 4) << 4);
                ldsm_x4_t(vh, va);
                ldsm_x4_t(vl, va + (SO_VLO - SO_VHI));
                mma_bf16(o[2 * dp],     &phi[4 * kc], vh[0], vh[1]);
                mma_bf16(o[2 * dp + 1], &phi[4 * kc], vh[2], vh[3]);
                mma_bf16(o[2 * dp],     &phi[4 * kc], vl[0], vl[1]);
                mma_bf16(o[2 * dp + 1], &phi[4 * kc], vl[2], vl[3]);
                mma_bf16(o[2 * dp],     &plo[4 * kc], vh[0], vh[1]);
                mma_bf16(o[2 * dp + 1], &plo[4 * kc], vh[2], vh[3]);
            }
        }
    }

    // ---- FIX: reduce quad-partial softmax denominators to full-row sums ----
    l1 += __shfl_xor_sync(0xffffffffu, l1, 1);
    l1 += __shfl_xor_sync(0xffffffffu, l1, 2);
    l2 += __shfl_xor_sync(0xffffffffu, l2, 1);
    l2 += __shfl_xor_sync(0xffffffffu, l2, 2);

    // ---- normalize + write ----
    float inv1 = 1.f / l1, inv2 = 1.f / l2;
    int row1 = b * kN + q0 + 16 * w + r1;
    #pragma unroll
    for (int db = 0; db < 4; db++) {
        int c = h * 32 + db * 8 + 2 * (lane & 3);
        *(float2*)(g_ao + (size_t)row1 * 256 + c) =
            make_float2(o[db][0] * inv1, o[db][1] * inv1);
        *(float2*)(g_ao + (size_t)(row1 + 8) * 256 + c) =
            make_float2(o[db][2] * inv2, o[db][3] * inv2);
    }
}

// ---------------- launch ----------------
extern "C" void kernel_launch(void* const* d_in, const int* in_sizes, int n_in,
                              void* d_out, int out_size)
{
    const float* hin   = (const float*)d_in[0];
    const float* coord = (const float*)d_in[1];
    const int*   mask  = (const int*)  d_in[2];
    const float* Wqkv  = (const float*)d_in[3];
    const float* bqkv  = (const float*)d_in[4];
    const float* Wproj = (const float*)d_in[5];
    const float* bproj = (const float*)d_in[6];
    const float* gamma = (const float*)d_in[7];
    const float* beta  = (const float*)d_in[8];
    const float* Wb1 = (const float*)d_in[9],  *bb1 = (const float*)d_in[10];
    const float* Wb2 = (const float*)d_in[11], *bb2 = (const float*)d_in[12];
    const float* Wb3 = (const float*)d_in[13], *bb3 = (const float*)d_in[14];
    float* out = (float*)d_out;

    void *p_xln, *p_qkv, *p_ao;
    cudaGetSymbolAddress(&p_xln, g_xln);
    cudaGetSymbolAddress(&p_qkv, g_qkv);
    cudaGetSymbolAddress(&p_ao,  g_ao);

    cudaFuncSetAttribute(attn_kernel, cudaFuncAttributeMaxDynamicSharedMemorySize, SMEM_BYTES);

    tab_kernel<<<kT / 256, 256>>>(Wb1, bb1, Wb2, bb2, Wb3, bb3);
    ln_kernel<<<kROWS, 256>>>(hin, gamma, beta);
    gemm64<<<dim3(768 / 64, kROWS / 64), 256>>>((const float*)p_xln, Wqkv, bqkv, nullptr,
                                                (float*)p_qkv, kROWS, 768, 256);
    attn_kernel<<<dim3(kN / 128, kNH, kB), 256, SMEM_BYTES>>>(coord, mask);
    gemm64<<<dim3(256 / 64, kROWS / 64), 256>>>((const float*)p_ao, Wproj, bproj, hin,
                                                out, kROWS, 256, 256);
}

// round 12
// speedup vs baseline: 2.3978x; 1.3986x over previous
#include <cuda_runtime.h>
#include <cuda_bf16.h>
#include <math.h>
#include <stdint.h>

typedef unsigned long long u64;
typedef uint32_t u32;

constexpr int kB = 4, kN = 1024, kNH = 8, kHID = 256;
constexpr int kROWS = kB * kN;
constexpr int kT = 2048;

// attn smem (bytes): TB 16384 | ck 256 | mk 256 | QHI/QLO 10240 | KHI/KLO/VHI/VLO 5120 each
constexpr int SO_CK  = 16384, SO_MK = 16640;
constexpr int SO_QHI = 16896, SO_QLO = 27136;
constexpr int SO_KHI = 37376, SO_KLO = 42496;
constexpr int SO_VHI = 47616, SO_VLO = 52736;
constexpr int SMEM_BYTES = 57856;

__device__ float g_xln[kROWS * kHID];
__device__ float g_qkv[kROWS * 3 * kHID];
__device__ float g_tab[kNH * kT];            // head-major, log2e pre-scaled
__device__ float g_ao [kROWS * kHID];

// ---------------- helpers ----------------
__device__ __forceinline__ u32 smem_u32(const void* p) {
    u32 a;
    asm("{ .reg .u64 t; cvta.to.shared.u64 t, %1; cvt.u32.u64 %0, t; }" : "=r"(a) : "l"(p));
    return a;
}
__device__ __forceinline__ void ldsm_x4(u32* r, u32 a) {
    asm volatile("ldmatrix.sync.aligned.m8n8.x4.shared.b16 {%0,%1,%2,%3}, [%4];"
        : "=r"(r[0]), "=r"(r[1]), "=r"(r[2]), "=r"(r[3]) : "r"(a));
}
__device__ __forceinline__ void ldsm_x4_t(u32* r, u32 a) {
    asm volatile("ldmatrix.sync.aligned.m8n8.x4.trans.shared.b16 {%0,%1,%2,%3}, [%4];"
        : "=r"(r[0]), "=r"(r[1]), "=r"(r[2]), "=r"(r[3]) : "r"(a));
}
__device__ __forceinline__ void mma_bf16(float* d, const u32* a, u32 b0, u32 b1) {
    asm volatile(
        "mma.sync.aligned.m16n8k16.row.col.f32.bf16.bf16.f32 "
        "{%0,%1,%2,%3}, {%4,%5,%6,%7}, {%8,%9}, {%0,%1,%2,%3};"
        : "+f"(d[0]), "+f"(d[1]), "+f"(d[2]), "+f"(d[3])
        : "r"(a[0]), "r"(a[1]), "r"(a[2]), "r"(a[3]), "r"(b0), "r"(b1));
}
__device__ __forceinline__ float ex2(float x) {
    float y; asm("ex2.approx.f32 %0, %1;" : "=f"(y) : "f"(x)); return y;
}
__device__ __forceinline__ u32 pk2(float a, float b) {
    __nv_bfloat162 t = __floats2bfloat162_rn(a, b);
    return *reinterpret_cast<u32*>(&t);
}
__device__ __forceinline__ float lo_f(u32 h) { return __uint_as_float(h << 16); }
__device__ __forceinline__ float hi_f(u32 h) { return __uint_as_float(h & 0xffff0000u); }

// stage [ROWS x 32] f32 (source row stride SSTR) into bf16 hi/lo smem, row stride 80B
template<int ROWS>
__device__ __forceinline__ void stage_mat(const float* src, int sstr, char* hib, char* lob,
                                          int t, float scale)
{
    #pragma unroll
    for (int i = 0; i < ROWS / 32; i++) {
        int idx = t + i * 256;
        int row = idx >> 3, d4 = (idx & 7) * 4;
        float4 v = *(const float4*)(src + (size_t)row * sstr + d4);
        float x0 = v.x * scale, x1 = v.y * scale, x2 = v.z * scale, x3 = v.w * scale;
        u32 h01 = pk2(x0, x1), h23 = pk2(x2, x3);
        u32 l01 = pk2(x0 - lo_f(h01), x1 - hi_f(h01));
        u32 l23 = pk2(x2 - lo_f(h23), x3 - hi_f(h23));
        int off = row * 80 + d4 * 2;
        *(uint2*)(hib + off) = make_uint2(h01, h23);
        *(uint2*)(lob + off) = make_uint2(l01, l23);
    }
}

// ---------------- LayerNorm ----------------
__global__ void ln_kernel(const float* __restrict__ hin, const float* __restrict__ gamma,
                          const float* __restrict__ beta)
{
    __shared__ float red[16];
    int row = blockIdx.x, t = threadIdx.x;
    float x = hin[(size_t)row * kHID + t];
    float s = x, s2 = x * x;
    #pragma unroll
    for (int off = 16; off; off >>= 1) {
        s  += __shfl_xor_sync(0xffffffffu, s,  off);
        s2 += __shfl_xor_sync(0xffffffffu, s2, off);
    }
    if ((t & 31) == 0) { red[t >> 5] = s; red[8 + (t >> 5)] = s2; }
    __syncthreads();
    float sum = 0.f, sum2 = 0.f;
    #pragma unroll
    for (int i = 0; i < 8; i++) { sum += red[i]; sum2 += red[8 + i]; }
    float mu = sum * (1.f / 256.f);
    float var = sum2 * (1.f / 256.f) - mu * mu;
    float r = rsqrtf(var + 1e-5f);
    g_xln[(size_t)row * kHID + t] = (x - mu) * r * gamma[t] + beta[t];
}

// ---------------- bias table ----------------
__global__ void __launch_bounds__(256) tab_kernel(
    const float* __restrict__ Wb1, const float* __restrict__ bb1,
    const float* __restrict__ Wb2, const float* __restrict__ bb2,
    const float* __restrict__ Wb3, const float* __restrict__ bb3)
{
    __shared__ float w1[64], c1[64], w2[4096], c2[64], w3[512], c3[8];
    int t = threadIdx.x;
    if (t < 64) { w1[t] = Wb1[t]; c1[t] = bb1[t]; c2[t] = bb2[t]; }
    if (t < 8)  c3[t] = bb3[t];
    for (int i = t; i < 4096; i += 256) w2[i] = Wb2[i];
    for (int i = t; i < 512;  i += 256) w3[i] = Wb3[i];
    __syncthreads();
    int idx = blockIdx.x * 256 + t;
    float d = -1.f + 2.f * (float)idx / (float)(kT - 1);
    float h1[64];
    #pragma unroll
    for (int u = 0; u < 64; u++) {
        float a = fmaf(d, w1[u], c1[u]);
        h1[u] = a / (1.f + expf(-a));
    }
    float acc[8];
    #pragma unroll
    for (int m = 0; m < 8; m++) acc[m] = c3[m];
    for (int u2 = 0; u2 < 64; u2++) {
        float a = c2[u2];
        #pragma unroll
        for (int u = 0; u < 64; u++) a = fmaf(h1[u], w2[u * 64 + u2], a);
        float sv = a / (1.f + expf(-a));
        #pragma unroll
        for (int m = 0; m < 8; m++) acc[m] = fmaf(sv, w3[u2 * 8 + m], acc[m]);
    }
    #pragma unroll
    for (int m = 0; m < 8; m++) g_tab[m * kT + idx] = acc[m] * 1.4426950408889634f;
}

// ---------------- HMMA GEMM: C[M,N] = A[M,K] @ W[K,N] + bias (+resid) ----------------
// CTA tile 128 x 64, 8 warps; warp w: rows 16w..16w+15. K chunks of 32.
__global__ void __launch_bounds__(256) gemm_h(
    const float* __restrict__ A, const float* __restrict__ W,
    const float* __restrict__ bias, const float* __restrict__ resid,
    float* __restrict__ C, int M, int N, int K)
{
    __shared__ char sAh[10240], sAl[10240];    // [128 rows][40 bf16] stride 80B
    __shared__ char sWh[4608],  sWl[4608];     // [32 k][72 bf16] stride 144B
    const u32 ah = smem_u32(sAh), al = smem_u32(sAl);
    const u32 wh_b = smem_u32(sWh), wl_b = smem_u32(sWl);

    const int n0 = blockIdx.x * 64, m0 = blockIdx.y * 128;
    const int t = threadIdx.x, w = t >> 5, lane = t & 31;
    const int r1 = lane >> 2;

    float o[8][4] = {};

    for (int k0 = 0; k0 < K; k0 += 32) {
        __syncthreads();
        // stage A chunk [128 x 32]
        stage_mat<128>(A + (size_t)m0 * K + k0, K, sAh, sAl, t, 1.f);
        // stage W chunk [32 k x 64 n], row stride 144B
        #pragma unroll
        for (int i = 0; i < 2; i++) {
            int idx = t + i * 256;
            int k = idx >> 4, c4 = (idx & 15) * 4;
            float4 v = *(const float4*)(W + (size_t)(k0 + k) * N + n0 + c4);
            u32 h01 = pk2(v.x, v.y), h23 = pk2(v.z, v.w);
            u32 l01 = pk2(v.x - lo_f(h01), v.y - hi_f(h01));
            u32 l23 = pk2(v.z - lo_f(h23), v.w - hi_f(h23));
            int off = k * 144 + c4 * 2;
            *(uint2*)(sWh + off) = make_uint2(h01, h23);
            *(uint2*)(sWl + off) = make_uint2(l01, l23);
        }
        __syncthreads();

        #pragma unroll
        for (int ks = 0; ks < 2; ks++) {
            u32 aAh[4], aAl[4];
            u32 qa = ah + (16 * w + (lane & 15)) * 80 + ks * 32 + ((lane >> 4) << 4);
            ldsm_x4(aAh, qa);
            ldsm_x4(aAl, qa + (al - ah));
            #pragma unroll
            for (int nb = 0; nb < 4; nb++) {
                u32 whf[4], wlf[4];
                u32 wa = wh_b + (ks * 16 + (lane & 15)) * 144 + nb * 32 + ((lane >> 4) << 4);
                ldsm_x4_t(whf, wa);
                ldsm_x4_t(wlf, wa + (wl_b - wh_b));
                mma_bf16(o[2 * nb],     aAh, whf[0], whf[1]);
                mma_bf16(o[2 * nb + 1], aAh, whf[2], whf[3]);
                mma_bf16(o[2 * nb],     aAl, whf[0], whf[1]);
                mma_bf16(o[2 * nb + 1], aAl, whf[2], whf[3]);
                mma_bf16(o[2 * nb],     aAh, wlf[0], wlf[1]);
                mma_bf16(o[2 * nb + 1], aAh, wlf[2], wlf[3]);
            }
        }
    }

    // epilogue
    int row1 = m0 + 16 * w + r1;
    #pragma unroll
    for (int nb2 = 0; nb2 < 8; nb2++) {
        int col = n0 + nb2 * 8 + 2 * (lane & 3);
        float b0 = bias[col], b1 = bias[col + 1];
        float v00 = o[nb2][0] + b0, v01 = o[nb2][1] + b1;
        float v10 = o[nb2][2] + b0, v11 = o[nb2][3] + b1;
        if (resid) {
            v00 += resid[(size_t)row1 * N + col];
            v01 += resid[(size_t)row1 * N + col + 1];
            v10 += resid[(size_t)(row1 + 8) * N + col];
            v11 += resid[(size_t)(row1 + 8) * N + col + 1];
        }
        *(float2*)(C + (size_t)row1 * N + col)       = make_float2(v00, v01);
        *(float2*)(C + (size_t)(row1 + 8) * N + col) = make_float2(v10, v11);
    }
}

// ---------------- HMMA flash attention, K-tile 64, 2 CTAs/SM ----------------
__global__ void __launch_bounds__(256, 2) attn_kernel(
    const float* __restrict__ coord, const int* __restrict__ mask)
{
    extern __shared__ char smc[];
    float2* TB2 = (float2*)smc;
    float*  ck  = (float*)(smc + SO_CK);
    int*    mkp = (int*)(smc + SO_MK);
    const u32 smb = smem_u32(smc);

    const int qt = blockIdx.x, h = blockIdx.y, b = blockIdx.z;
    const int q0 = qt * 128;
    const int t = threadIdx.x, w = t >> 5, lane = t & 31;

    #pragma unroll
    for (int i = 0; i < 8; i++) {
        int idx = t + i * 256;
        float f0 = g_tab[h * kT + idx];
        float f1 = g_tab[h * kT + (idx < kT - 1 ? idx + 1 : kT - 1)];
        TB2[idx] = make_float2(f0, f1);
    }
    const float QSCALE = 1.4426950408889634f / 5.656854249492381f;
    stage_mat<128>(g_qkv + (size_t)(b * kN + q0) * 768 + h * 32, 768,
                   smc + SO_QHI, smc + SO_QLO, t, QSCALE);
    __syncthreads();

    u32 aQh[2][4], aQl[2][4];
    {
        u32 qa = smb + SO_QHI + (16 * w + (lane & 15)) * 80 + ((lane >> 4) << 4);
        ldsm_x4(aQh[0], qa);
        ldsm_x4(aQh[1], qa + 32);
        ldsm_x4(aQl[0], qa + (SO_QLO - SO_QHI));
        ldsm_x4(aQl[1], qa + (SO_QLO - SO_QHI) + 32);
    }

    const int r1 = lane >> 2;
    const float cq1 = coord[b * kN + q0 + 16 * w + r1];
    const float cq2 = coord[b * kN + q0 + 16 * w + r1 + 8];
    const float aq1 = fmaf(-cq1, 1023.5f, 1023.5f);
    const float aq2 = fmaf(-cq2, 1023.5f, 1023.5f);

    float m1 = -1e30f, m2 = -1e30f, l1 = 0.f, l2 = 0.f;
    float o[4][4] = {};

    for (int tile = 0; tile < 16; tile++) {
        const int j0 = tile * 64;
        __syncthreads();
        stage_mat<64>(g_qkv + (size_t)(b * kN + j0) * 768 + 256 + h * 32, 768,
                      smc + SO_KHI, smc + SO_KLO, t, 1.f);
        stage_mat<64>(g_qkv + (size_t)(b * kN + j0) * 768 + 512 + h * 32, 768,
                      smc + SO_VHI, smc + SO_VLO, t, 1.f);
        if (t < 64) { ck[t] = coord[b * kN + j0 + t]; mkp[t] = mask[b * kN + j0 + t]; }
        __syncthreads();

        // ---- S = Q K^T (16 rows x 64 cols per warp) ----
        float sacc[8][4];
        #pragma unroll
        for (int i = 0; i < 8; i++)
            { sacc[i][0] = 0.f; sacc[i][1] = 0.f; sacc[i][2] = 0.f; sacc[i][3] = 0.f; }
        #pragma unroll
        for (int ks = 0; ks < 2; ks++) {
            #pragma unroll
            for (int nb = 0; nb < 4; nb++) {
                u32 kh[4], kl[4];
                u32 ka = smb + SO_KHI + (nb * 16 + (lane & 15)) * 80 + ks * 32 + ((lane >> 4) << 4);
                ldsm_x4(kh, ka);
                ldsm_x4(kl, ka + (SO_KLO - SO_KHI));
                mma_bf16(sacc[2 * nb],     aQh[ks], kh[0], kh[2]);
                mma_bf16(sacc[2 * nb + 1], aQh[ks], kh[1], kh[3]);
                mma_bf16(sacc[2 * nb],     aQl[ks], kh[0], kh[2]);
                mma_bf16(sacc[2 * nb + 1], aQl[ks], kh[1], kh[3]);
                mma_bf16(sacc[2 * nb],     aQh[ks], kl[0], kl[2]);
                mma_bf16(sacc[2 * nb + 1], aQh[ks], kl[1], kl[3]);
            }
        }

        // ---- softmax pass 1 ----
        float mx1 = m1, mx2 = m2;
        #pragma unroll
        for (int cb = 0; cb < 8; cb++) {
            int c0 = cb * 8 + 2 * (lane & 3);
            float ck0 = ck[c0], ck1 = ck[c0 + 1];
            int mk0 = mkp[c0], mk1 = mkp[c0 + 1];
            float u00 = fmaf(ck0, 1023.5f, aq1), u01 = fmaf(ck1, 1023.5f, aq1);
            float u10 = fmaf(ck0, 1023.5f, aq2), u11 = fmaf(ck1, 1023.5f, aq2);
            int i00 = (int)u00, i01 = (int)u01, i10 = (int)u10, i11 = (int)u11;
            float2 t00 = TB2[i00], t01 = TB2[i01], t10 = TB2[i10], t11 = TB2[i11];
            float s00 = sacc[cb][0] + fmaf(u00 - (float)i00, t00.y - t00.x, t00.x);
            float s01 = sacc[cb][1] + fmaf(u01 - (float)i01, t01.y - t01.x, t01.x);
            float s10 = sacc[cb][2] + fmaf(u10 - (float)i10, t10.y - t10.x, t10.x);
            float s11 = sacc[cb][3] + fmaf(u11 - (float)i11, t11.y - t11.x, t11.x);
            if (!mk0) { s00 = -1e38f; s10 = -1e38f; }
            if (!mk1) { s01 = -1e38f; s11 = -1e38f; }
            sacc[cb][0] = s00; sacc[cb][1] = s01; sacc[cb][2] = s10; sacc[cb][3] = s11;
            mx1 = fmaxf(mx1, fmaxf(s00, s01));
            mx2 = fmaxf(mx2, fmaxf(s10, s11));
        }
        mx1 = fmaxf(mx1, __shfl_xor_sync(0xffffffffu, mx1, 1));
        mx1 = fmaxf(mx1, __shfl_xor_sync(0xffffffffu, mx1, 2));
        mx2 = fmaxf(mx2, __shfl_xor_sync(0xffffffffu, mx2, 1));
        mx2 = fmaxf(mx2, __shfl_xor_sync(0xffffffffu, mx2, 2));
        float co1 = ex2(m1 - mx1), co2 = ex2(m2 - mx2);
        m1 = mx1; m2 = mx2;
        #pragma unroll
        for (int db = 0; db < 4; db++) {
            o[db][0] *= co1; o[db][1] *= co1; o[db][2] *= co2; o[db][3] *= co2;
        }

        // ---- pass 2: p = exp2(s - m); P hi/lo A-fragments in registers ----
        float su1 = 0.f, su2 = 0.f;
        u32 phi[16], plo[16];
        #pragma unroll
        for (int cb = 0; cb < 8; cb++) {
            float p00 = ex2(sacc[cb][0] - m1), p01 = ex2(sacc[cb][1] - m1);
            float p10 = ex2(sacc[cb][2] - m2), p11 = ex2(sacc[cb][3] - m2);
            su1 += p00 + p01; su2 += p10 + p11;
            u32 hA = pk2(p00, p01);
            phi[2 * cb] = hA;
            plo[2 * cb] = pk2(p00 - lo_f(hA), p01 - hi_f(hA));
            u32 hB = pk2(p10, p11);
            phi[2 * cb + 1] = hB;
            plo[2 * cb + 1] = pk2(p10 - lo_f(hB), p11 - hi_f(hB));
        }
        // su quad-partial; valid since co is quad-uniform; reduced after the loop
        l1 = l1 * co1 + su1;
        l2 = l2 * co2 + su2;

        // ---- O += P V ----
        #pragma unroll
        for (int kc = 0; kc < 4; kc++) {
            #pragma unroll
            for (int dp = 0; dp < 2; dp++) {
                u32 vh[4], vl[4];
                u32 va = smb + SO_VHI + (16 * kc + (lane & 15)) * 80 + dp * 32 + ((lane >> 4) << 4);
                ldsm_x4_t(vh, va);
                ldsm_x4_t(vl, va + (SO_VLO - SO_VHI));
                mma_bf16(o[2 * dp],     &phi[4 * kc], vh[0], vh[1]);
                mma_bf16(o[2 * dp + 1], &phi[4 * kc], vh[2], vh[3]);
                mma_bf16(o[2 * dp],     &phi[4 * kc], vl[0], vl[1]);
                mma_bf16(o[2 * dp + 1], &phi[4 * kc], vl[2], vl[3]);
                mma_bf16(o[2 * dp],     &plo[4 * kc], vh[0], vh[1]);
                mma_bf16(o[2 * dp + 1], &plo[4 * kc], vh[2], vh[3]);
            }
        }
    }

    // reduce quad-partial denominators to full-row sums
    l1 += __shfl_xor_sync(0xffffffffu, l1, 1);
    l1 += __shfl_xor_sync(0xffffffffu, l1, 2);
    l2 += __shfl_xor_sync(0xffffffffu, l2, 1);
    l2 += __shfl_xor_sync(0xffffffffu, l2, 2);

    float inv1 = 1.f / l1, inv2 = 1.f / l2;
    int row1 = b * kN + q0 + 16 * w + r1;
    #pragma unroll
    for (int db = 0; db < 4; db++) {
        int c = h * 32 + db * 8 + 2 * (lane & 3);
        *(float2*)(g_ao + (size_t)row1 * 256 + c) =
            make_float2(o[db][0] * inv1, o[db][1] * inv1);
        *(float2*)(g_ao + (size_t)(row1 + 8) * 256 + c) =
            make_float2(o[db][2] * inv2, o[db][3] * inv2);
    }
}

// ---------------- launch ----------------
extern "C" void kernel_launch(void* const* d_in, const int* in_sizes, int n_in,
                              void* d_out, int out_size)
{
    const float* hin   = (const float*)d_in[0];
    const float* coord = (const float*)d_in[1];
    const int*   mask  = (const int*)  d_in[2];
    const float* Wqkv  = (const float*)d_in[3];
    const float* bqkv  = (const float*)d_in[4];
    const float* Wproj = (const float*)d_in[5];
    const float* bproj = (const float*)d_in[6];
    const float* gamma = (const float*)d_in[7];
    const float* beta  = (const float*)d_in[8];
    const float* Wb1 = (const float*)d_in[9],  *bb1 = (const float*)d_in[10];
    const float* Wb2 = (const float*)d_in[11], *bb2 = (const float*)d_in[12];
    const float* Wb3 = (const float*)d_in[13], *bb3 = (const float*)d_in[14];
    float* out = (float*)d_out;

    void *p_xln, *p_qkv, *p_ao;
    cudaGetSymbolAddress(&p_xln, g_xln);
    cudaGetSymbolAddress(&p_qkv, g_qkv);
    cudaGetSymbolAddress(&p_ao,  g_ao);

    cudaFuncSetAttribute(attn_kernel, cudaFuncAttributeMaxDynamicSharedMemorySize, SMEM_BYTES);

    tab_kernel<<<kT / 256, 256>>>(Wb1, bb1, Wb2, bb2, Wb3, bb3);
    ln_kernel<<<kROWS, 256>>>(hin, gamma, beta);
    // qkv = xln @ Wqkv + bqkv   [4096 x 768]
    gemm_h<<<dim3(768 / 64, kROWS / 128), 256>>>((const float*)p_xln, Wqkv, bqkv, nullptr,
                                                 (float*)p_qkv, kROWS, 768, 256);
    attn_kernel<<<dim3(kN / 128, kNH, kB), 256, SMEM_BYTES>>>(coord, mask);
    // out = h + ao @ Wproj + bproj   [4096 x 256]
    gemm_h<<<dim3(256 / 64, kROWS / 128), 256>>>((const float*)p_ao, Wproj, bproj, hin,
                                                 out, kROWS, 256, 256);
}